// round 1
// baseline (speedup 1.0000x reference)
#include <cuda_runtime.h>

#define N_NODES 50000
#define N_EDGES 800000
#define DIM     128
#define DV      32          // DIM/4 float4 per row
#define EPSN    1e-12f

// ---------------- static device scratch (no allocations allowed) ----------------
__device__ float  g_deg[N_NODES];
__device__ int    g_cnt[N_NODES];
__device__ int    g_cur[N_NODES];
__device__ int    g_rowptr[N_NODES + 1];
__device__ int    g_cols[N_EDGES];
__device__ float  g_vals[N_EDGES];
__device__ float4 g_x0[N_NODES * DV];
__device__ float4 g_x1[N_NODES * DV];
__device__ float  g_colsum[DIM];
__device__ float  g_colsq[DIM];

// ---------------- kernels ----------------

__global__ void k_init()
{
    int i = blockIdx.x * blockDim.x + threadIdx.x;
    if (i < N_NODES) {
        g_deg[i] = 0.0f;
        g_cnt[i] = 0;
        g_cur[i] = 0;
    }
    if (i < DIM) {
        g_colsum[i] = 0.0f;
        g_colsq[i]  = 0.0f;
    }
}

__global__ void k_hist(const int* __restrict__ erow, const float* __restrict__ eval)
{
    int e = blockIdx.x * blockDim.x + threadIdx.x;
    if (e < N_EDGES) {
        int r = erow[e];
        atomicAdd(&g_deg[r], eval[e]);
        atomicAdd(&g_cnt[r], 1);
    }
}

// Single-block exclusive scan of g_cnt -> g_rowptr (50001 entries).
__global__ void k_scan()
{
    __shared__ int sh[1024];
    const int t  = threadIdx.x;
    const int CH = (N_NODES + 1023) / 1024;   // 49
    int beg = t * CH;
    int end = min(beg + CH, N_NODES);

    int s = 0;
    for (int i = beg; i < end; i++) s += g_cnt[i];
    sh[t] = s;
    __syncthreads();
    // inclusive Hillis-Steele scan over 1024 partials
    for (int off = 1; off < 1024; off <<= 1) {
        int v = (t >= off) ? sh[t - off] : 0;
        __syncthreads();
        sh[t] += v;
        __syncthreads();
    }
    int run = (t == 0) ? 0 : sh[t - 1];
    for (int i = beg; i < end; i++) {
        g_rowptr[i] = run;
        run += g_cnt[i];
    }
    if (t == 0) g_rowptr[N_NODES] = N_EDGES;
}

__global__ void k_scatter(const int* __restrict__ erow, const int* __restrict__ ecol,
                          const float* __restrict__ eval)
{
    int e = blockIdx.x * blockDim.x + threadIdx.x;
    if (e < N_EDGES) {
        int r = erow[e];
        int p = g_rowptr[r] + atomicAdd(&g_cur[r], 1);
        g_cols[p] = ecol[e];
        g_vals[p] = eval[e];
    }
}

// x0 = R * deg^(-1/2) (deg==0 -> 1), and zero d_out (acc buffer).
__global__ void k_initx(const float4* __restrict__ R, float4* __restrict__ acc)
{
    int i = blockIdx.x * blockDim.x + threadIdx.x;
    if (i < N_NODES * DV) {
        int node = i >> 5;
        float d = g_deg[node];
        if (d == 0.0f) d = 1.0f;
        float s = rsqrtf(d);
        float4 r = R[i];
        g_x0[i] = make_float4(r.x * s, r.y * s, r.z * s, r.w * s);
        acc[i]  = make_float4(0.f, 0.f, 0.f, 0.f);
    }
}

// One warp per row. xin/xout selected by flip. Fused: SpMM, inv-deg scale,
// L2-norm (warp shuffle reduce), weighted accumulation into acc (=d_out).
__global__ __launch_bounds__(256) void k_spmm(int flip, float4* __restrict__ acc, float w)
{
    int gtid = blockIdx.x * blockDim.x + threadIdx.x;
    int row  = gtid >> 5;
    int lane = threadIdx.x & 31;
    if (row >= N_NODES) return;

    const float4* __restrict__ xin  = flip ? g_x1 : g_x0;
    float4*       __restrict__ xout = flip ? g_x0 : g_x1;

    int s = g_rowptr[row];
    int e = g_rowptr[row + 1];

    float ax = 0.f, ay = 0.f, az = 0.f, aw = 0.f;

    int j = s;
    for (; j + 4 <= e; j += 4) {
        int   c0 = g_cols[j],   c1 = g_cols[j + 1], c2 = g_cols[j + 2], c3 = g_cols[j + 3];
        float v0 = g_vals[j],   v1 = g_vals[j + 1], v2 = g_vals[j + 2], v3 = g_vals[j + 3];
        float4 p0 = xin[c0 * DV + lane];
        float4 p1 = xin[c1 * DV + lane];
        float4 p2 = xin[c2 * DV + lane];
        float4 p3 = xin[c3 * DV + lane];
        ax += v0 * p0.x; ay += v0 * p0.y; az += v0 * p0.z; aw += v0 * p0.w;
        ax += v1 * p1.x; ay += v1 * p1.y; az += v1 * p1.z; aw += v1 * p1.w;
        ax += v2 * p2.x; ay += v2 * p2.y; az += v2 * p2.z; aw += v2 * p2.w;
        ax += v3 * p3.x; ay += v3 * p3.y; az += v3 * p3.z; aw += v3 * p3.w;
    }
    for (; j < e; j++) {
        int   c = g_cols[j];
        float v = g_vals[j];
        float4 p = xin[c * DV + lane];
        ax += v * p.x; ay += v * p.y; az += v * p.z; aw += v * p.w;
    }

    float d = g_deg[row];
    if (d == 0.0f) d = 1.0f;
    float id = 1.0f / d;
    ax *= id; ay *= id; az *= id; aw *= id;

    float ss = ax * ax + ay * ay + az * az + aw * aw;
    #pragma unroll
    for (int o = 16; o; o >>= 1) ss += __shfl_xor_sync(0xffffffffu, ss, o);

    float nrm = fmaxf(sqrtf(ss), EPSN);
    float sc  = w / nrm;

    int base = row * DV + lane;
    xout[base] = make_float4(ax, ay, az, aw);
    float4 a = acc[base];
    acc[base] = make_float4(a.x + sc * ax, a.y + sc * ay, a.z + sc * az, a.w + sc * aw);
}

// Per-column sum and sum-of-squares partial reduction. blockDim = 128 (one col per thread).
__global__ void k_colreduce(const float* __restrict__ acc)
{
    int c = threadIdx.x;
    float s = 0.f, q = 0.f;
    for (int r = blockIdx.x; r < N_NODES; r += gridDim.x) {
        float v = acc[r * DIM + c];
        s += v;
        q += v * v;
    }
    atomicAdd(&g_colsum[c], s);
    atomicAdd(&g_colsq[c], q);
}

__global__ void k_std(float* __restrict__ out)
{
    int i = blockIdx.x * blockDim.x + threadIdx.x;
    if (i < N_NODES * DIM) {
        int c = i & (DIM - 1);
        const float n = (float)N_NODES;
        float mean = g_colsum[c] / n;
        float var  = (g_colsq[c] - n * mean * mean) / (n - 1.0f);
        var = fmaxf(var, 0.0f);
        float sd = sqrtf(var);
        if (sd == 0.0f) sd = 1.0f;
        out[i] = (out[i] - mean) / sd;
    }
}

// ---------------- launcher ----------------

extern "C" void kernel_launch(void* const* d_in, const int* in_sizes, int n_in,
                              void* d_out, int out_size)
{
    const int*   erow = (const int*)d_in[0];
    const int*   ecol = (const int*)d_in[1];
    const float* eval = (const float*)d_in[2];
    const float* R    = (const float*)d_in[3];
    float*       out  = (float*)d_out;

    const float W[4] = {1.0f, 1.0f, 7.81f, 45.28f};

    k_init<<<(N_NODES + 255) / 256, 256>>>();
    k_hist<<<(N_EDGES + 255) / 256, 256>>>(erow, eval);
    k_scan<<<1, 1024>>>();
    k_scatter<<<(N_EDGES + 255) / 256, 256>>>(erow, ecol, eval);
    k_initx<<<(N_NODES * DV + 255) / 256, 256>>>((const float4*)R, (float4*)d_out);

    // 8 warps per block -> 6250 blocks cover 50000 rows
    const int spmm_blocks = (N_NODES * 32 + 255) / 256;
    for (int i = 0; i < 4; i++) {
        k_spmm<<<spmm_blocks, 256>>>(i & 1, (float4*)d_out, W[i]);
    }

    k_colreduce<<<256, DIM>>>(out);
    k_std<<<(N_NODES * DIM + 255) / 256, 256>>>(out);
}